// round 12
// baseline (speedup 1.0000x reference)
#include <cuda_runtime.h>
#include <cuda_fp16.h>
#include <cstdint>
#include <math.h>

#define N_NODES 50000
#define N_EDGES 800000
#define IN_FEAT 512
#define OUT_FEAT 128

#define LO_SCALE 2048.0f
#define LO_INV   (1.0f / 2048.0f)

// Scratch buffers.
__device__ float  g_x[(size_t)N_NODES * OUT_FEAT];
__device__ int    g_row_ptr[N_NODES + 1];
// fp16 B fragments (m16n8k16): slot = s*16 + nbg (s 0..31, nbg 0..15),
// idx = slot*32 + lane; n = nbg*8 + (lane>>2), k = s*16 + 2*(lane&3);
// value {f16x2(hiB[k],hiB[k+1]), f16x2(hiB[k+8],hiB[k+9]),
//        f16x2(loB_s[k],loB_s[k+1]), f16x2(loB_s[k+8],loB_s[k+9])}
// where hiB = fp16(B), loB_s = fp16(2048*(B - hiB)).                 (256 KB)
__device__ uint4 g_Bf16[32 * 16 * 32];

__device__ __forceinline__ uint32_t h2_bits(__half2 h) { return *(uint32_t*)&h; }

// ---------------------------------------------------------------------------
// Kernel 1 (merged): CSR row pointers (edge-boundary scatter) + B fragment
// table build. Independent work, one launch.
// ---------------------------------------------------------------------------
__global__ void prep_kernel(const int* __restrict__ rows,
                            const float* __restrict__ B) {
    const int t = blockIdx.x * blockDim.x + threadIdx.x;

    // ---- B fragments (first 16384 threads) ----
    if (t < 32 * 16 * 32) {
        const int lane = t & 31, nbg = (t >> 5) & 15, s = t >> 9;
        const int t4 = lane & 3, g = lane >> 2;
        const int n = nbg * 8 + g;
        const int k = s * 16 + 2 * t4;
        const float b0 = __ldg(&B[(size_t)(k + 0) * OUT_FEAT + n]);
        const float b1 = __ldg(&B[(size_t)(k + 1) * OUT_FEAT + n]);
        const float b8 = __ldg(&B[(size_t)(k + 8) * OUT_FEAT + n]);
        const float b9 = __ldg(&B[(size_t)(k + 9) * OUT_FEAT + n]);
        __half2 h01 = __floats2half2_rn(b0, b1);
        __half2 h89 = __floats2half2_rn(b8, b9);
        float2 f01 = __half22float2(h01);
        float2 f89 = __half22float2(h89);
        __half2 l01 = __floats2half2_rn((b0 - f01.x) * LO_SCALE, (b1 - f01.y) * LO_SCALE);
        __half2 l89 = __floats2half2_rn((b8 - f89.x) * LO_SCALE, (b9 - f89.y) * LO_SCALE);
        g_Bf16[t] = make_uint4(h2_bits(h01), h2_bits(h89), h2_bits(l01), h2_bits(l89));
    }

    // ---- row_ptr scatter ----
    const int e0 = t * 4;
    if (e0 >= N_EDGES) return;
    const int4 r4 = *(const int4*)&rows[e0];
    int prev = (t == 0) ? -1 : __ldg(&rows[e0 - 1]);
    int rv[4] = {r4.x, r4.y, r4.z, r4.w};
    #pragma unroll
    for (int j = 0; j < 4; ++j) {
        for (int r = prev + 1; r <= rv[j]; ++r) g_row_ptr[r] = e0 + j;
        prev = rv[j];
    }
    if (e0 + 4 == N_EDGES) {
        for (int r = prev + 1; r <= N_NODES; ++r) g_row_ptr[r] = N_EDGES;
    }
}

// ---------------------------------------------------------------------------
// Kernel 2: GEMM  g_x[M,128] = feat[M,512] @ W[512,128]
// fp16 2-accumulator split (hi + scaled-lo, fp32 accum):
//   c += hiA*hiB ; c2 += loA_s*hiB + hiA*loB_s ; final = c + c2/2048.
// CTA tile 16(M) x 128(N), 128 threads, warp tile 16x32 — small c footprint
// (~100 regs) to reach 4-5 CTAs/SM = 6+ warps/SMSP for latency hiding.
// A staged reg-split -> SMEM double buffered; B register-prefetched 1 step.
// ---------------------------------------------------------------------------
#define BM 16
#define KC 32
#define NCHUNK (IN_FEAT / KC)     // 16
#define NSTEP 32
#define AB_STRIDE 20              // f16x2 words per A row (16 + 4 pad)

#define MMA_F16(cc, aa, b0, b1)                                                \
    asm volatile(                                                              \
        "mma.sync.aligned.m16n8k16.row.col.f32.f16.f16.f32 "                   \
        "{%0,%1,%2,%3}, {%4,%5,%6,%7}, {%8,%9}, {%0,%1,%2,%3};"                \
        : "+f"((cc)[0]), "+f"((cc)[1]), "+f"((cc)[2]), "+f"((cc)[3])           \
        : "r"((aa)[0]), "r"((aa)[1]), "r"((aa)[2]), "r"((aa)[3]),              \
          "r"(b0), "r"(b1))

__global__ __launch_bounds__(128, 4) void gemm_mma_kernel(
    const float* __restrict__ A)   // feat [N_NODES, 512]
{
    __shared__ uint32_t sAh[2][BM * AB_STRIDE];   // fp16x2 hi
    __shared__ uint32_t sAl[2][BM * AB_STRIDE];   // fp16x2 scaled lo

    const int tid  = threadIdx.x;
    const int wn   = tid >> 5;
    const int lane = tid & 31;
    const int g    = lane >> 2;
    const int t4   = lane & 3;
    const int m0   = blockIdx.x * BM;

    // A fill: 16 rows x 8 float4 slots = 128, exactly 1 per thread.
    const int fmr = tid >> 3;
    const int fk4 = tid & 7;

    float4 pf;
    auto ldgA = [&](int ch) {
        const int gm = m0 + fmr;
        pf = make_float4(0.f, 0.f, 0.f, 0.f);
        if (gm < N_NODES)
            pf = *(const float4*)&A[(size_t)gm * IN_FEAT + ch * KC + fk4 * 4];
    };
    auto stsA = [&](int b) {
        __half2 h01 = __floats2half2_rn(pf.x, pf.y);
        __half2 h23 = __floats2half2_rn(pf.z, pf.w);
        float2 f01 = __half22float2(h01);
        float2 f23 = __half22float2(h23);
        __half2 l01 = __floats2half2_rn((pf.x - f01.x) * LO_SCALE,
                                        (pf.y - f01.y) * LO_SCALE);
        __half2 l23 = __floats2half2_rn((pf.z - f23.x) * LO_SCALE,
                                        (pf.w - f23.y) * LO_SCALE);
        const int w = fmr * AB_STRIDE + fk4 * 2;
        *(uint2*)&sAh[b][w] = make_uint2(h2_bits(h01), h2_bits(h23));
        *(uint2*)&sAl[b][w] = make_uint2(h2_bits(l01), h2_bits(l23));
    };

    // B register banks by step parity.
    uint4 bf[2][4];
    auto ldB = [&](int s, int p) {
        #pragma unroll
        for (int nb = 0; nb < 4; ++nb)
            bf[p][nb] = __ldg(&g_Bf16[(size_t)(s * 16 + wn * 4 + nb) * 32 + lane]);
    };

    float c[4][4], c2[4][4];
    #pragma unroll
    for (int j = 0; j < 4; j++)
        #pragma unroll
        for (int q = 0; q < 4; q++) { c[j][q] = 0.0f; c2[j][q] = 0.0f; }

    ldB(0, 0);
    ldgA(0);
    stsA(0);

    for (int ch = 0; ch < NCHUNK; ++ch) {
        const int buf = ch & 1;
        if (ch + 1 < NCHUNK) ldgA(ch + 1);
        __syncthreads();

        const uint32_t* ahp = sAh[buf];
        const uint32_t* alp = sAl[buf];

        #pragma unroll
        for (int ks2 = 0; ks2 < 2; ++ks2) {
            const int s = ch * 2 + ks2;
            const int p = s & 1;
            if (s + 1 < NSTEP) ldB(s + 1, p ^ 1);   // prefetch next step's B

            const int w0 = g * AB_STRIDE + ks2 * 8 + t4;
            const int w8 = (g + 8) * AB_STRIDE + ks2 * 8 + t4;
            uint32_t ah[4], al[4];
            ah[0] = ahp[w0];     ah[1] = ahp[w8];
            ah[2] = ahp[w0 + 4]; ah[3] = ahp[w8 + 4];
            al[0] = alp[w0];     al[1] = alp[w8];
            al[2] = alp[w0 + 4]; al[3] = alp[w8 + 4];

            #pragma unroll
            for (int nb = 0; nb < 4; ++nb) {
                MMA_F16(c [nb], ah, bf[p][nb].x, bf[p][nb].y);  // hi*hi
                MMA_F16(c2[nb], al, bf[p][nb].x, bf[p][nb].y);  // loA_s*hiB
                MMA_F16(c2[nb], ah, bf[p][nb].z, bf[p][nb].w);  // hiA*loB_s
            }
        }

        if (ch + 1 < NCHUNK) stsA(buf ^ 1);
    }

    // ---- epilogue: combine main + scaled corrections ----
    #pragma unroll
    for (int half = 0; half < 2; ++half) {
        const int row = m0 + g + half * 8;
        if (row < N_NODES) {
            #pragma unroll
            for (int nb = 0; nb < 4; ++nb) {
                const int col = wn * 32 + nb * 8 + 2 * t4;
                float2 v = make_float2(
                    fmaf(c2[nb][2 * half],     LO_INV, c[nb][2 * half]),
                    fmaf(c2[nb][2 * half + 1], LO_INV, c[nb][2 * half + 1]));
                *(float2*)&g_x[(size_t)row * OUT_FEAT + col] = v;
            }
        }
    }
}

// ---------------------------------------------------------------------------
// Kernel 3: SpMM (warp per row, no atomics) + multispike epilogue.
// At the LTS cap with compulsory traffic — unchanged.
// ---------------------------------------------------------------------------
__device__ __forceinline__ float multispike(float x) {
    return floorf(fminf(fmaxf(4.0f * x, 0.0f), 4.0f) + 0.5f) * 0.25f;
}

__global__ __launch_bounds__(256) void spmm_kernel(
    const int*   __restrict__ cols,
    const float* __restrict__ ew,
    float*       __restrict__ out)
{
    const int warp = (blockIdx.x * blockDim.x + threadIdx.x) >> 5;
    const int lane = threadIdx.x & 31;
    if (warp >= N_NODES) return;

    const int e0 = g_row_ptr[warp];
    const int e1 = g_row_ptr[warp + 1];

    float4 acc = make_float4(0.f, 0.f, 0.f, 0.f);
    const int fo = lane * 4;

    int e = e0;
    for (; e + 3 < e1; e += 4) {
        int   cc[4];
        float ww[4];
        #pragma unroll
        for (int j = 0; j < 4; ++j) { cc[j] = __ldg(&cols[e + j]); ww[j] = __ldg(&ew[e + j]); }
        #pragma unroll
        for (int j = 0; j < 4; ++j) {
            const float4 v = *(const float4*)&g_x[(size_t)cc[j] * OUT_FEAT + fo];
            acc.x = fmaf(ww[j], v.x, acc.x); acc.y = fmaf(ww[j], v.y, acc.y);
            acc.z = fmaf(ww[j], v.z, acc.z); acc.w = fmaf(ww[j], v.w, acc.w);
        }
    }
    for (; e < e1; ++e) {
        const int   c0 = __ldg(&cols[e]);
        const float w0 = __ldg(&ew[e]);
        const float4 v0 = *(const float4*)&g_x[(size_t)c0 * OUT_FEAT + fo];
        acc.x = fmaf(w0, v0.x, acc.x); acc.y = fmaf(w0, v0.y, acc.y);
        acc.z = fmaf(w0, v0.z, acc.z); acc.w = fmaf(w0, v0.w, acc.w);
    }

    acc.x = multispike(acc.x);
    acc.y = multispike(acc.y);
    acc.z = multispike(acc.z);
    acc.w = multispike(acc.w);
    *(float4*)&out[(size_t)warp * OUT_FEAT + fo] = acc;
}

// ---------------------------------------------------------------------------
extern "C" void kernel_launch(void* const* d_in, const int* in_sizes, int n_in,
                              void* d_out, int out_size) {
    const float* feat   = (const float*)d_in[0];
    const float* weight = (const float*)d_in[1];
    const int*   rows   = (const int*)d_in[2];
    const int*   cols   = (const int*)d_in[3];
    const float* ew     = (const float*)d_in[4];
    float* out = (float*)d_out;

    prep_kernel<<<(N_EDGES / 4 + 256) / 256, 256>>>(rows, weight);
    gemm_mma_kernel<<<(N_NODES + BM - 1) / BM, 128>>>(feat);
    spmm_kernel<<<(N_NODES * 32 + 255) / 256, 256>>>(cols, ew, out);
}